// round 15
// baseline (speedup 1.0000x reference)
#include <cuda_runtime.h>
#include <cstdint>

// ---------------------------------------------------------------------------
// SymmetrizeRotavg — converged structure (best: 252.4us at R14).
//   scaled[n]   = inv_lat[b(n)]^T @ forces[n]
//   acc[symm_map[n,o]] += rot[o] @ scaled[n]   (o = 0..O-1)
//   out[n]      = lat[b(n)]^T @ (acc[n] / O)
//
// The scatter's REDG queue floor is ~245us, but R12-R14 proved per-thread
// issue work is PARTIALLY EXPOSED (-2.5, -3.1, -2.1us from integer trims).
// R15 attacks the two biggest remaining instruction blocks:
//   - LDS: pair-interleaved 10-float (40B) rot layout -> LDS.64 rows,
//     20 LDS/thread instead of 36. Bank-conflict-free: (o*10+c) mod 32 is
//     distinct for all 12 warp-resident o values (unlike R3's 48B stride).
//   - FMA: packed fma.rn.f32x2 for the (x,y) rows -> 28 math instrs vs 36.
// Fallback kernels and periphery unchanged (frozen since R11).
// ---------------------------------------------------------------------------

#define MAX_N (1 << 20)   // N = 1,048,576 for this problem
#define MAX_O 64

__device__ float4 g_scaled[MAX_N];
__device__ float4 g_acc[MAX_N];

// Stage 1: scaled = inv_lat^T f ; zero the accumulator.
__global__ __launch_bounds__(256) void k_prep(
    const float* __restrict__ inv_lat,
    const float* __restrict__ forces,
    int N, int A)
{
    int n = blockIdx.x * blockDim.x + threadIdx.x;
    if (n >= N) return;
    int b = n / A;
    float f0 = forces[3 * n + 0];
    float f1 = forces[3 * n + 1];
    float f2 = forces[3 * n + 2];
    const float* M = inv_lat + 9 * b;   // M[j*3+i]
    float s0 = M[0] * f0 + M[3] * f1 + M[6] * f2;
    float s1 = M[1] * f0 + M[4] * f1 + M[7] * f2;
    float s2 = M[2] * f0 + M[5] * f1 + M[8] * f2;
    g_scaled[n] = make_float4(s0, s1, s2, 0.0f);
    g_acc[n]    = make_float4(0.0f, 0.0f, 0.0f, 0.0f);
}

// --- packed f32x2 helpers -------------------------------------------------
__device__ __forceinline__ uint64_t pack2(float lo, float hi)
{
    uint64_t r;
    asm("mov.b64 %0, {%1, %2};" : "=l"(r) : "f"(lo), "f"(hi));
    return r;
}
__device__ __forceinline__ void unpack2(uint64_t p, float& lo, float& hi)
{
    asm("mov.b64 {%0, %1}, %2;" : "=f"(lo), "=f"(hi) : "l"(p));
}
__device__ __forceinline__ uint64_t mul2(uint64_t a, uint64_t b)
{
    uint64_t r;
    asm("mul.rn.f32x2 %0, %1, %2;" : "=l"(r) : "l"(a), "l"(b));
    return r;
}
__device__ __forceinline__ uint64_t fma2(uint64_t a, uint64_t b, uint64_t c)
{
    uint64_t r;
    asm("fma.rn.f32x2 %0, %1, %2, %3;" : "=l"(r) : "l"(a), "l"(b), "l"(c));
    return r;
}

// red on a precomputed GLOBAL address (cvta hoisted to caller).
__device__ __forceinline__ void red_add_v4_g(uint64_t gaddr, float x, float y, float z)
{
    asm volatile(
        "red.global.add.v4.f32 [%0], {%1, %2, %3, %4};"
        :: "l"(gaddr), "f"(x), "f"(y), "f"(z), "f"(0.0f)
        : "memory");
}

__device__ __forceinline__ void red_add_v4(float4* p, float x, float y, float z)
{
    asm volatile(
        "{\n\t"
        ".reg .u64 ga;\n\t"
        "cvta.to.global.u64 ga, %0;\n\t"
        "red.global.add.v4.f32 [ga], {%1, %2, %3, %4};\n\t"
        "}"
        :: "l"(p), "f"(x), "f"(y), "f"(z), "f"(0.0f)
        : "memory");
}

__device__ __forceinline__ uint64_t to_global_u64(const void* p)
{
    uint64_t g;
    asm("cvta.to.global.u64 %0, %1;" : "=l"(g) : "l"(p));
    return g;
}

// Stage 2 (floor-pinned): one thread = one n and 4 consecutive ops.
// srot layout per o (10 floats, 40B): [R00,R10, R01,R11, R02,R12, R20,R21,R22, pad]
// -> (x,y) rows as LDS.64 pairs feeding fma.rn.f32x2; z row scalar.
template<int O>
__global__ __launch_bounds__(256) void k_scatterT(
    const float* __restrict__ gops,   // (O,4,4)
    const int*   __restrict__ smap,   // (N,O)
    int N)
{
    constexpr int PER_N = O / 4;
    __shared__ float srot[O * 10];
    // src offsets within a (4,4) op for the interleaved layout
    const int src_off[10] = {0, 4, 1, 5, 2, 6, 8, 9, 10, 0};
#pragma unroll
    for (int t = threadIdx.x; t < O * 10; t += 256) {
        int o = t / 10;
        int e = t - o * 10;
        srot[t] = (e == 9) ? 0.0f : __ldg(gops + o * 16 + src_off[e]);
    }
    __syncthreads();

    unsigned int idx = blockIdx.x * 256u + threadIdx.x;   // < N*PER_N < 2^31
    unsigned int total = (unsigned int)N * PER_N;
    if (idx >= total) return;
    unsigned int n = idx / PER_N;            // 32-bit const-div
    unsigned int k = idx - n * PER_N;

    float4 s = g_scaled[n];
    uint64_t sxx = pack2(s.x, s.x);
    uint64_t syy = pack2(s.y, s.y);
    uint64_t szz = pack2(s.z, s.z);

    int4 t4 = *reinterpret_cast<const int4*>(smap + (size_t)n * O + k * 4);

    uint64_t acc_base = to_global_u64(g_acc);

#pragma unroll
    for (int r = 0; r < 4; r++) {
        int o = k * 4 + r;
        const float* R = srot + o * 10;
        // LDS.64 pairs: (R00,R10), (R01,R11), (R02,R12)
        uint64_t q0 = *reinterpret_cast<const uint64_t*>(R + 0);
        uint64_t q1 = *reinterpret_cast<const uint64_t*>(R + 2);
        uint64_t q2 = *reinterpret_cast<const uint64_t*>(R + 4);
        float2  z01 = *reinterpret_cast<const float2*>(R + 6);
        float   z2  = R[8];

        uint64_t pxy = fma2(q0, sxx, fma2(q1, syy, mul2(q2, szz)));
        float x, y;
        unpack2(pxy, x, y);
        float z = z01.x * s.x + z01.y * s.y + z2 * s.z;

        int tgt = (r == 0) ? t4.x : (r == 1) ? t4.y : (r == 2) ? t4.z : t4.w;
        uint64_t gaddr = acc_base + ((uint64_t)(unsigned int)tgt << 4);
        red_add_v4_g(gaddr, x, y, z);
    }
}

// Runtime-O variant (O multiple of 4 but not 32/48/64) — plain layout.
__global__ __launch_bounds__(256) void k_scatter4(
    const float* __restrict__ gops,
    const int*   __restrict__ smap,
    int N, int O)
{
    __shared__ float srot[MAX_O * 9];
    for (int t = threadIdx.x; t < O * 9; t += blockDim.x) {
        int o = t / 9;
        int e = t - o * 9;
        int i = e / 3;
        int j = e - i * 3;
        srot[t] = gops[o * 16 + i * 4 + j];
    }
    __syncthreads();

    int per_n = O >> 2;
    long long idx = (long long)blockIdx.x * blockDim.x + threadIdx.x;
    long long total = (long long)N * per_n;
    if (idx >= total) return;
    int n = (int)(idx / per_n);
    int k = (int)(idx - (long long)n * per_n);

    float4 s = g_scaled[n];
    int4 t4 = *reinterpret_cast<const int4*>(smap + (long long)n * O + k * 4);
    int tgt[4] = { t4.x, t4.y, t4.z, t4.w };

#pragma unroll
    for (int r = 0; r < 4; r++) {
        int o = k * 4 + r;
        const float* R = srot + o * 9;
        float x = R[0] * s.x + R[1] * s.y + R[2] * s.z;
        float y = R[3] * s.x + R[4] * s.y + R[5] * s.z;
        float z = R[6] * s.x + R[7] * s.y + R[8] * s.z;
        red_add_v4(&g_acc[tgt[r]], x, y, z);
    }
}

// Fallback (O not a multiple of 4): one thread per (n,o).
__global__ __launch_bounds__(256) void k_scatter1(
    const float* __restrict__ gops,
    const int*   __restrict__ smap,
    int N, int O)
{
    __shared__ float srot[MAX_O * 9];
    for (int t = threadIdx.x; t < O * 9; t += blockDim.x) {
        int o = t / 9;
        int e = t - o * 9;
        int i = e / 3;
        int j = e - i * 3;
        srot[t] = gops[o * 16 + i * 4 + j];
    }
    __syncthreads();

    long long idx = (long long)blockIdx.x * blockDim.x + threadIdx.x;
    long long total = (long long)N * O;
    if (idx >= total) return;
    int n = (int)(idx / O);
    int o = (int)(idx - (long long)n * O);

    float4 s = g_scaled[n];
    int tgt = smap[(long long)n * O + o];
    const float* R = srot + o * 9;
    float x = R[0] * s.x + R[1] * s.y + R[2] * s.z;
    float y = R[3] * s.x + R[4] * s.y + R[5] * s.z;
    float z = R[6] * s.x + R[7] * s.y + R[8] * s.z;
    red_add_v4(&g_acc[tgt], x, y, z);
}

// Stage 3: out = lat^T (acc / O). One atom per thread (acc is L2-hot).
__global__ __launch_bounds__(256) void k_final(
    const float* __restrict__ lat,
    float* __restrict__ out,
    int N, int A, float inv_count)
{
    int n = blockIdx.x * blockDim.x + threadIdx.x;
    if (n >= N) return;
    int b = n / A;
    float4 a = g_acc[n];
    float s0 = a.x * inv_count;
    float s1 = a.y * inv_count;
    float s2 = a.z * inv_count;
    const float* L = lat + 9 * b;   // L[j*3+i]
    out[3 * n + 0] = L[0] * s0 + L[3] * s1 + L[6] * s2;
    out[3 * n + 1] = L[1] * s0 + L[4] * s1 + L[7] * s2;
    out[3 * n + 2] = L[2] * s0 + L[5] * s1 + L[8] * s2;
}

extern "C" void kernel_launch(void* const* d_in, const int* in_sizes, int n_in,
                              void* d_out, int out_size)
{
    const float* lattices     = (const float*)d_in[0];  // (B,3,3)
    const float* inv_lattices = (const float*)d_in[1];  // (B,3,3)
    const float* forces       = (const float*)d_in[2];  // (N,3)
    // d_in[3] = num_atoms (int64, uniform A)
    const float* general_ops  = (const float*)d_in[4];  // (O,4,4)
    const int*   symm_map     = (const int*)d_in[5];    // (N,O)
    // d_in[6] = num_general_ops (int64, uniform O)

    int B = in_sizes[0] / 9;
    int N = in_sizes[2] / 3;
    int O = in_sizes[4] / 16;
    int A = N / B;

    float* out = (float*)d_out;

    const int TPB = 256;
    int blocks_n = (N + TPB - 1) / TPB;

    k_prep<<<blocks_n, TPB>>>(inv_lattices, forces, N, A);

    long long total4 = (long long)N * (O >> 2);
    bool fits32 = total4 < 0x7FFFFFFFLL;

    if (O == 48 && fits32) {
        int blocks = (int)((total4 + TPB - 1) / TPB);
        k_scatterT<48><<<blocks, TPB>>>(general_ops, symm_map, N);
    } else if (O == 32 && fits32) {
        int blocks = (int)((total4 + TPB - 1) / TPB);
        k_scatterT<32><<<blocks, TPB>>>(general_ops, symm_map, N);
    } else if (O == 64 && fits32) {
        int blocks = (int)((total4 + TPB - 1) / TPB);
        k_scatterT<64><<<blocks, TPB>>>(general_ops, symm_map, N);
    } else if ((O & 3) == 0) {
        int blocks = (int)((total4 + TPB - 1) / TPB);
        k_scatter4<<<blocks, TPB>>>(general_ops, symm_map, N, O);
    } else {
        long long total = (long long)N * O;
        int blocks = (int)((total + TPB - 1) / TPB);
        k_scatter1<<<blocks, TPB>>>(general_ops, symm_map, N, O);
    }

    k_final<<<blocks_n, TPB>>>(lattices, out, N, A, 1.0f / (float)O);
}

// round 16
// speedup vs baseline: 1.1682x; 1.1682x over previous
#include <cuda_runtime.h>
#include <cstdint>

// ---------------------------------------------------------------------------
// SymmetrizeRotavg — FINAL converged form (R14, best: 252.4us).
//   scaled[n]   = inv_lat[b(n)]^T @ forces[n]
//   acc[symm_map[n,o]] += rot[o] @ scaled[n]   (o = 0..O-1)
//   out[n]      = lat[b(n)]^T @ (acc[n] / O)
//
// Scatter at ~97% of the B300 spread-REDG floor (50.3M red.v4 lanes x 1.29
// cyc/lane / 148 SMs). Session findings (R1-R15):
//   - red.v4 moves 16B/lane at scalar-lane cost — widest available reduction
//   - lane count algorithmically irreducible (random map)
//   - exposed per-thread ALU trims won: templated divisor (-2.5us, R12),
//     templated O (-3.1us, R13), 32-bit index + hoisted cvta (-2.1us, R14)
//   - smem rot layout changes LOSE: float4 tiles +170us (R3), pair-interleaved
//     LDS.64 + f32x2 +44us (R15, two-phase LDS.64 conflicts). Scalar LDS with
//     36B stride is conflict-free and final.
//   - coarsening short memory kernels loses (R3/R7/R10)
//   - periphery variants all tied; this is the measured minimum.
// ---------------------------------------------------------------------------

#define MAX_N (1 << 20)   // N = 1,048,576 for this problem
#define MAX_O 64

__device__ float4 g_scaled[MAX_N];
__device__ float4 g_acc[MAX_N];

// Stage 1: scaled = inv_lat^T f ; zero the accumulator (every launch, so
// graph replays are deterministic). One atom per thread.
__global__ __launch_bounds__(256) void k_prep(
    const float* __restrict__ inv_lat,
    const float* __restrict__ forces,
    int N, int A)
{
    int n = blockIdx.x * blockDim.x + threadIdx.x;
    if (n >= N) return;
    int b = n / A;
    float f0 = forces[3 * n + 0];
    float f1 = forces[3 * n + 1];
    float f2 = forces[3 * n + 2];
    const float* M = inv_lat + 9 * b;   // M[j*3+i]
    float s0 = M[0] * f0 + M[3] * f1 + M[6] * f2;
    float s1 = M[1] * f0 + M[4] * f1 + M[7] * f2;
    float s2 = M[2] * f0 + M[5] * f1 + M[8] * f2;
    g_scaled[n] = make_float4(s0, s1, s2, 0.0f);
    g_acc[n]    = make_float4(0.0f, 0.0f, 0.0f, 0.0f);
}

// red on a precomputed GLOBAL address (cvta hoisted to caller).
__device__ __forceinline__ void red_add_v4_g(uint64_t gaddr, float x, float y, float z)
{
    asm volatile(
        "red.global.add.v4.f32 [%0], {%1, %2, %3, %4};"
        :: "l"(gaddr), "f"(x), "f"(y), "f"(z), "f"(0.0f)
        : "memory");
}

__device__ __forceinline__ void red_add_v4(float4* p, float x, float y, float z)
{
    asm volatile(
        "{\n\t"
        ".reg .u64 ga;\n\t"
        "cvta.to.global.u64 ga, %0;\n\t"
        "red.global.add.v4.f32 [ga], {%1, %2, %3, %4};\n\t"
        "}"
        :: "l"(p), "f"(x), "f"(y), "f"(z), "f"(0.0f)
        : "memory");
}

__device__ __forceinline__ uint64_t to_global_u64(const void* p)
{
    uint64_t g;
    asm("cvta.to.global.u64 %0, %1;" : "=l"(g) : "l"(p));
    return g;
}

// Stage 2 (floor-pinned): one thread = one n and 4 consecutive ops.
// O compile-time; ALL index math 32-bit (N*PER_N < 2^31); one cvta per
// thread (g_acc base), targets addressed via IMAD.WIDE on tgt*16.
// Scalar smem rot loads (36B stride, bank-conflict free), int4 smap load.
template<int O>
__global__ __launch_bounds__(256) void k_scatterT(
    const float* __restrict__ gops,   // (O,4,4)
    const int*   __restrict__ smap,   // (N,O)
    int N)
{
    constexpr int PER_N = O / 4;
    __shared__ float srot[O * 9];
#pragma unroll
    for (int t = threadIdx.x; t < O * 9; t += 256) {
        int o = t / 9;
        int e = t - o * 9;
        int i = e / 3;
        int j = e - i * 3;
        srot[t] = __ldg(gops + o * 16 + i * 4 + j);
    }
    __syncthreads();

    unsigned int idx = blockIdx.x * 256u + threadIdx.x;   // < N*PER_N < 2^31
    unsigned int total = (unsigned int)N * PER_N;
    if (idx >= total) return;
    unsigned int n = idx / PER_N;            // 32-bit const-div -> IMAD.HI+shift
    unsigned int k = idx - n * PER_N;

    float4 s = g_scaled[n];
    int4 t4 = *reinterpret_cast<const int4*>(smap + (size_t)n * O + k * 4);

    uint64_t acc_base = to_global_u64(g_acc);

#pragma unroll
    for (int r = 0; r < 4; r++) {
        int o = k * 4 + r;
        const float* R = srot + o * 9;   // R[i*3+j]
        float x = R[0] * s.x + R[1] * s.y + R[2] * s.z;
        float y = R[3] * s.x + R[4] * s.y + R[5] * s.z;
        float z = R[6] * s.x + R[7] * s.y + R[8] * s.z;
        int tgt = (r == 0) ? t4.x : (r == 1) ? t4.y : (r == 2) ? t4.z : t4.w;
        uint64_t gaddr = acc_base + ((uint64_t)(unsigned int)tgt << 4);
        red_add_v4_g(gaddr, x, y, z);
    }
}

// Runtime-O variant (O multiple of 4 but not 32/48/64).
__global__ __launch_bounds__(256) void k_scatter4(
    const float* __restrict__ gops,
    const int*   __restrict__ smap,
    int N, int O)
{
    __shared__ float srot[MAX_O * 9];
    for (int t = threadIdx.x; t < O * 9; t += blockDim.x) {
        int o = t / 9;
        int e = t - o * 9;
        int i = e / 3;
        int j = e - i * 3;
        srot[t] = gops[o * 16 + i * 4 + j];
    }
    __syncthreads();

    int per_n = O >> 2;
    long long idx = (long long)blockIdx.x * blockDim.x + threadIdx.x;
    long long total = (long long)N * per_n;
    if (idx >= total) return;
    int n = (int)(idx / per_n);
    int k = (int)(idx - (long long)n * per_n);

    float4 s = g_scaled[n];
    int4 t4 = *reinterpret_cast<const int4*>(smap + (long long)n * O + k * 4);
    int tgt[4] = { t4.x, t4.y, t4.z, t4.w };

#pragma unroll
    for (int r = 0; r < 4; r++) {
        int o = k * 4 + r;
        const float* R = srot + o * 9;
        float x = R[0] * s.x + R[1] * s.y + R[2] * s.z;
        float y = R[3] * s.x + R[4] * s.y + R[5] * s.z;
        float z = R[6] * s.x + R[7] * s.y + R[8] * s.z;
        red_add_v4(&g_acc[tgt[r]], x, y, z);
    }
}

// Fallback (O not a multiple of 4): one thread per (n,o).
__global__ __launch_bounds__(256) void k_scatter1(
    const float* __restrict__ gops,
    const int*   __restrict__ smap,
    int N, int O)
{
    __shared__ float srot[MAX_O * 9];
    for (int t = threadIdx.x; t < O * 9; t += blockDim.x) {
        int o = t / 9;
        int e = t - o * 9;
        int i = e / 3;
        int j = e - i * 3;
        srot[t] = gops[o * 16 + i * 4 + j];
    }
    __syncthreads();

    long long idx = (long long)blockIdx.x * blockDim.x + threadIdx.x;
    long long total = (long long)N * O;
    if (idx >= total) return;
    int n = (int)(idx / O);
    int o = (int)(idx - (long long)n * O);

    float4 s = g_scaled[n];
    int tgt = smap[(long long)n * O + o];
    const float* R = srot + o * 9;
    float x = R[0] * s.x + R[1] * s.y + R[2] * s.z;
    float y = R[3] * s.x + R[4] * s.y + R[5] * s.z;
    float z = R[6] * s.x + R[7] * s.y + R[8] * s.z;
    red_add_v4(&g_acc[tgt], x, y, z);
}

// Stage 3: out = lat^T (acc / O). One atom per thread (acc is L2-hot).
__global__ __launch_bounds__(256) void k_final(
    const float* __restrict__ lat,
    float* __restrict__ out,
    int N, int A, float inv_count)
{
    int n = blockIdx.x * blockDim.x + threadIdx.x;
    if (n >= N) return;
    int b = n / A;
    float4 a = g_acc[n];
    float s0 = a.x * inv_count;
    float s1 = a.y * inv_count;
    float s2 = a.z * inv_count;
    const float* L = lat + 9 * b;   // L[j*3+i]
    out[3 * n + 0] = L[0] * s0 + L[3] * s1 + L[6] * s2;
    out[3 * n + 1] = L[1] * s0 + L[4] * s1 + L[7] * s2;
    out[3 * n + 2] = L[2] * s0 + L[5] * s1 + L[8] * s2;
}

extern "C" void kernel_launch(void* const* d_in, const int* in_sizes, int n_in,
                              void* d_out, int out_size)
{
    const float* lattices     = (const float*)d_in[0];  // (B,3,3)
    const float* inv_lattices = (const float*)d_in[1];  // (B,3,3)
    const float* forces       = (const float*)d_in[2];  // (N,3)
    // d_in[3] = num_atoms (int64, uniform A)
    const float* general_ops  = (const float*)d_in[4];  // (O,4,4)
    const int*   symm_map     = (const int*)d_in[5];    // (N,O)
    // d_in[6] = num_general_ops (int64, uniform O)

    int B = in_sizes[0] / 9;
    int N = in_sizes[2] / 3;
    int O = in_sizes[4] / 16;
    int A = N / B;

    float* out = (float*)d_out;

    const int TPB = 256;
    int blocks_n = (N + TPB - 1) / TPB;

    k_prep<<<blocks_n, TPB>>>(inv_lattices, forces, N, A);

    // 32-bit templated path requires N*(O/4) < 2^31 (true here: 12.6M).
    long long total4 = (long long)N * (O >> 2);
    bool fits32 = total4 < 0x7FFFFFFFLL;

    if (O == 48 && fits32) {
        int blocks = (int)((total4 + TPB - 1) / TPB);
        k_scatterT<48><<<blocks, TPB>>>(general_ops, symm_map, N);
    } else if (O == 32 && fits32) {
        int blocks = (int)((total4 + TPB - 1) / TPB);
        k_scatterT<32><<<blocks, TPB>>>(general_ops, symm_map, N);
    } else if (O == 64 && fits32) {
        int blocks = (int)((total4 + TPB - 1) / TPB);
        k_scatterT<64><<<blocks, TPB>>>(general_ops, symm_map, N);
    } else if ((O & 3) == 0) {
        int blocks = (int)((total4 + TPB - 1) / TPB);
        k_scatter4<<<blocks, TPB>>>(general_ops, symm_map, N, O);
    } else {
        long long total = (long long)N * O;
        int blocks = (int)((total + TPB - 1) / TPB);
        k_scatter1<<<blocks, TPB>>>(general_ops, symm_map, N, O);
    }

    k_final<<<blocks_n, TPB>>>(lattices, out, N, A, 1.0f / (float)O);
}

// round 17
// speedup vs baseline: 1.1717x; 1.0030x over previous
#include <cuda_runtime.h>
#include <cstdint>

// ---------------------------------------------------------------------------
// SymmetrizeRotavg — converged form (best: 252.4us at R14).
//   scaled[n]   = inv_lat[b(n)]^T @ forces[n]
//   acc[symm_map[n,o]] += rot[o] @ scaled[n]   (o = 0..O-1)
//   out[n]      = lat[b(n)]^T @ (acc[n] / O)
//
// Scatter at ~97% of the B300 spread-REDG floor (50.3M red.v4 lanes x 1.29
// cyc/lane / 148 SMs). Session findings (R1-R16):
//   - exposed per-thread ALU trims won: templated divisor (-2.5us, R12),
//     templated O (-3.1us, R13), 32-bit index + hoisted cvta (-2.1us, R14)
//   - smem rot layout changes LOSE (R3 +170us, R15 +44.6us) -> scalar LDS
//   - coarsening short memory kernels loses (R3/R7/R10)
//   - R17: isolated test of ld.global.cs on the one-shot 192MB symm_map
//     stream (evict-first), protecting the 16MB g_acc L2 working set from
//     eviction by the streaming map lines.
// ---------------------------------------------------------------------------

#define MAX_N (1 << 20)   // N = 1,048,576 for this problem
#define MAX_O 64

__device__ float4 g_scaled[MAX_N];
__device__ float4 g_acc[MAX_N];

// Stage 1: scaled = inv_lat^T f ; zero the accumulator (every launch, so
// graph replays are deterministic). One atom per thread.
__global__ __launch_bounds__(256) void k_prep(
    const float* __restrict__ inv_lat,
    const float* __restrict__ forces,
    int N, int A)
{
    int n = blockIdx.x * blockDim.x + threadIdx.x;
    if (n >= N) return;
    int b = n / A;
    float f0 = forces[3 * n + 0];
    float f1 = forces[3 * n + 1];
    float f2 = forces[3 * n + 2];
    const float* M = inv_lat + 9 * b;   // M[j*3+i]
    float s0 = M[0] * f0 + M[3] * f1 + M[6] * f2;
    float s1 = M[1] * f0 + M[4] * f1 + M[7] * f2;
    float s2 = M[2] * f0 + M[5] * f1 + M[8] * f2;
    g_scaled[n] = make_float4(s0, s1, s2, 0.0f);
    g_acc[n]    = make_float4(0.0f, 0.0f, 0.0f, 0.0f);
}

// red on a precomputed GLOBAL address (cvta hoisted to caller).
__device__ __forceinline__ void red_add_v4_g(uint64_t gaddr, float x, float y, float z)
{
    asm volatile(
        "red.global.add.v4.f32 [%0], {%1, %2, %3, %4};"
        :: "l"(gaddr), "f"(x), "f"(y), "f"(z), "f"(0.0f)
        : "memory");
}

__device__ __forceinline__ void red_add_v4(float4* p, float x, float y, float z)
{
    asm volatile(
        "{\n\t"
        ".reg .u64 ga;\n\t"
        "cvta.to.global.u64 ga, %0;\n\t"
        "red.global.add.v4.f32 [ga], {%1, %2, %3, %4};\n\t"
        "}"
        :: "l"(p), "f"(x), "f"(y), "f"(z), "f"(0.0f)
        : "memory");
}

__device__ __forceinline__ uint64_t to_global_u64(const void* p)
{
    uint64_t g;
    asm("cvta.to.global.u64 %0, %1;" : "=l"(g) : "l"(p));
    return g;
}

// Evict-first streaming int4 load (one-shot data; keep it out of L2's way).
__device__ __forceinline__ int4 ldcs_int4(const int* p)
{
    int4 v;
    asm volatile("ld.global.cs.v4.s32 {%0,%1,%2,%3}, [%4];"
                 : "=r"(v.x), "=r"(v.y), "=r"(v.z), "=r"(v.w)
                 : "l"(p));
    return v;
}

// Stage 2 (floor-pinned): one thread = one n and 4 consecutive ops.
// O compile-time; ALL index math 32-bit (N*PER_N < 2^31); one cvta per
// thread (g_acc base), targets addressed via IMAD.WIDE on tgt*16.
// Scalar smem rot loads (36B stride, bank-conflict free), int4 smap load
// with evict-first policy.
template<int O>
__global__ __launch_bounds__(256) void k_scatterT(
    const float* __restrict__ gops,   // (O,4,4)
    const int*   __restrict__ smap,   // (N,O)
    int N)
{
    constexpr int PER_N = O / 4;
    __shared__ float srot[O * 9];
#pragma unroll
    for (int t = threadIdx.x; t < O * 9; t += 256) {
        int o = t / 9;
        int e = t - o * 9;
        int i = e / 3;
        int j = e - i * 3;
        srot[t] = __ldg(gops + o * 16 + i * 4 + j);
    }
    __syncthreads();

    unsigned int idx = blockIdx.x * 256u + threadIdx.x;   // < N*PER_N < 2^31
    unsigned int total = (unsigned int)N * PER_N;
    if (idx >= total) return;
    unsigned int n = idx / PER_N;            // 32-bit const-div -> IMAD.HI+shift
    unsigned int k = idx - n * PER_N;

    float4 s = g_scaled[n];
    int4 t4 = ldcs_int4(smap + (size_t)n * O + k * 4);

    uint64_t acc_base = to_global_u64(g_acc);

#pragma unroll
    for (int r = 0; r < 4; r++) {
        int o = k * 4 + r;
        const float* R = srot + o * 9;   // R[i*3+j]
        float x = R[0] * s.x + R[1] * s.y + R[2] * s.z;
        float y = R[3] * s.x + R[4] * s.y + R[5] * s.z;
        float z = R[6] * s.x + R[7] * s.y + R[8] * s.z;
        int tgt = (r == 0) ? t4.x : (r == 1) ? t4.y : (r == 2) ? t4.z : t4.w;
        uint64_t gaddr = acc_base + ((uint64_t)(unsigned int)tgt << 4);
        red_add_v4_g(gaddr, x, y, z);
    }
}

// Runtime-O variant (O multiple of 4 but not 32/48/64).
__global__ __launch_bounds__(256) void k_scatter4(
    const float* __restrict__ gops,
    const int*   __restrict__ smap,
    int N, int O)
{
    __shared__ float srot[MAX_O * 9];
    for (int t = threadIdx.x; t < O * 9; t += blockDim.x) {
        int o = t / 9;
        int e = t - o * 9;
        int i = e / 3;
        int j = e - i * 3;
        srot[t] = gops[o * 16 + i * 4 + j];
    }
    __syncthreads();

    int per_n = O >> 2;
    long long idx = (long long)blockIdx.x * blockDim.x + threadIdx.x;
    long long total = (long long)N * per_n;
    if (idx >= total) return;
    int n = (int)(idx / per_n);
    int k = (int)(idx - (long long)n * per_n);

    float4 s = g_scaled[n];
    int4 t4 = *reinterpret_cast<const int4*>(smap + (long long)n * O + k * 4);
    int tgt[4] = { t4.x, t4.y, t4.z, t4.w };

#pragma unroll
    for (int r = 0; r < 4; r++) {
        int o = k * 4 + r;
        const float* R = srot + o * 9;
        float x = R[0] * s.x + R[1] * s.y + R[2] * s.z;
        float y = R[3] * s.x + R[4] * s.y + R[5] * s.z;
        float z = R[6] * s.x + R[7] * s.y + R[8] * s.z;
        red_add_v4(&g_acc[tgt[r]], x, y, z);
    }
}

// Fallback (O not a multiple of 4): one thread per (n,o).
__global__ __launch_bounds__(256) void k_scatter1(
    const float* __restrict__ gops,
    const int*   __restrict__ smap,
    int N, int O)
{
    __shared__ float srot[MAX_O * 9];
    for (int t = threadIdx.x; t < O * 9; t += blockDim.x) {
        int o = t / 9;
        int e = t - o * 9;
        int i = e / 3;
        int j = e - i * 3;
        srot[t] = gops[o * 16 + i * 4 + j];
    }
    __syncthreads();

    long long idx = (long long)blockIdx.x * blockDim.x + threadIdx.x;
    long long total = (long long)N * O;
    if (idx >= total) return;
    int n = (int)(idx / O);
    int o = (int)(idx - (long long)n * O);

    float4 s = g_scaled[n];
    int tgt = smap[(long long)n * O + o];
    const float* R = srot + o * 9;
    float x = R[0] * s.x + R[1] * s.y + R[2] * s.z;
    float y = R[3] * s.x + R[4] * s.y + R[5] * s.z;
    float z = R[6] * s.x + R[7] * s.y + R[8] * s.z;
    red_add_v4(&g_acc[tgt], x, y, z);
}

// Stage 3: out = lat^T (acc / O). One atom per thread (acc is L2-hot).
__global__ __launch_bounds__(256) void k_final(
    const float* __restrict__ lat,
    float* __restrict__ out,
    int N, int A, float inv_count)
{
    int n = blockIdx.x * blockDim.x + threadIdx.x;
    if (n >= N) return;
    int b = n / A;
    float4 a = g_acc[n];
    float s0 = a.x * inv_count;
    float s1 = a.y * inv_count;
    float s2 = a.z * inv_count;
    const float* L = lat + 9 * b;   // L[j*3+i]
    out[3 * n + 0] = L[0] * s0 + L[3] * s1 + L[6] * s2;
    out[3 * n + 1] = L[1] * s0 + L[4] * s1 + L[7] * s2;
    out[3 * n + 2] = L[2] * s0 + L[5] * s1 + L[8] * s2;
}

extern "C" void kernel_launch(void* const* d_in, const int* in_sizes, int n_in,
                              void* d_out, int out_size)
{
    const float* lattices     = (const float*)d_in[0];  // (B,3,3)
    const float* inv_lattices = (const float*)d_in[1];  // (B,3,3)
    const float* forces       = (const float*)d_in[2];  // (N,3)
    // d_in[3] = num_atoms (int64, uniform A)
    const float* general_ops  = (const float*)d_in[4];  // (O,4,4)
    const int*   symm_map     = (const int*)d_in[5];    // (N,O)
    // d_in[6] = num_general_ops (int64, uniform O)

    int B = in_sizes[0] / 9;
    int N = in_sizes[2] / 3;
    int O = in_sizes[4] / 16;
    int A = N / B;

    float* out = (float*)d_out;

    const int TPB = 256;
    int blocks_n = (N + TPB - 1) / TPB;

    k_prep<<<blocks_n, TPB>>>(inv_lattices, forces, N, A);

    // 32-bit templated path requires N*(O/4) < 2^31 (true here: 12.6M).
    long long total4 = (long long)N * (O >> 2);
    bool fits32 = total4 < 0x7FFFFFFFLL;

    if (O == 48 && fits32) {
        int blocks = (int)((total4 + TPB - 1) / TPB);
        k_scatterT<48><<<blocks, TPB>>>(general_ops, symm_map, N);
    } else if (O == 32 && fits32) {
        int blocks = (int)((total4 + TPB - 1) / TPB);
        k_scatterT<32><<<blocks, TPB>>>(general_ops, symm_map, N);
    } else if (O == 64 && fits32) {
        int blocks = (int)((total4 + TPB - 1) / TPB);
        k_scatterT<64><<<blocks, TPB>>>(general_ops, symm_map, N);
    } else if ((O & 3) == 0) {
        int blocks = (int)((total4 + TPB - 1) / TPB);
        k_scatter4<<<blocks, TPB>>>(general_ops, symm_map, N, O);
    } else {
        long long total = (long long)N * O;
        int blocks = (int)((total + TPB - 1) / TPB);
        k_scatter1<<<blocks, TPB>>>(general_ops, symm_map, N, O);
    }

    k_final<<<blocks_n, TPB>>>(lattices, out, N, A, 1.0f / (float)O);
}